// round 11
// baseline (speedup 1.0000x reference)
#include <cuda_runtime.h>

// Problem constants (B=1, H=32, Q=1024, S=4096, D=128)
#define SEQ      4096
#define ROWS     32768      // B*H*Q rows of attn_weights
#define START    4
#define HEAVY    409        // int(4096*0.1)
#define RSTART   3687       // 4096 - min(409,512)
#define NCAND    3683       // RSTART - START
#define NKEEP    822        // 4 + 409 + 409
#define HEADS    32
#define NBLK     148        // one exact wave, all co-resident
#define NTHR     1024
#define ICH      25         // candidates per block in rank phase (148*25>=3683)
#define TOTAL_G  (2*HEADS*NKEEP*32)   // full gather float4 count = 1,683,456
#define KVF4     (HEADS*SEQ*32)       // float4 count per KV tensor = 4,194,304

// Scratch. g_sums is atomically accumulated so it MUST be zero at entry:
// the tail kernel's last block re-zeroes it (all consumers done by then).
__device__ double g_sums[SEQ];
__device__ int    g_rank[NCAND];
__device__ int    g_cnt;      // tail grid barrier
__device__ int    g_done;     // tail epilogue counter
__device__ float  g_dummy[NBLK];   // prefetch sink (write-only)

// ================= Kernel 1: column sums (512 MB PURE READ stream) =========
// 148 blocks, contiguous row range each (measured ~82us @ ~83% DRAM).
// Thread t owns columns [4t,4t+4) via float4; 8 front-batched LDG.128
// (MLP=8); __ldcs (no reuse). fp32 over 32 rows flushed into fp64 keeps the
// mean accurate to ~1e-8 rel (top-k boundary gap ~1e-5); fp64 atomicAdd
// ordering noise ~1e-13 — selection identical to reference (rel_err 0.0).
__global__ void __launch_bounds__(NTHR, 1) k_colsum(const float* __restrict__ w) {
    const int t = threadIdx.x;
    const int b = blockIdx.x;
    const int r0 = (int)((long long)ROWS * b / NBLK);
    const int r1 = (int)((long long)ROWS * (b + 1) / NBLK);
    const float4* __restrict__ w4 = (const float4*)w + t;
    double a0 = 0, a1 = 0, a2 = 0, a3 = 0;
    float  c0 = 0, c1 = 0, c2 = 0, c3 = 0;
    int row = r0, grp = 0;
    for (; row + 8 <= r1; row += 8) {
        float4 v[8];
        #pragma unroll
        for (int k = 0; k < 8; k++)
            v[k] = __ldcs(&w4[(size_t)(row + k) * 1024]);
        float s0x = (v[0].x + v[1].x) + (v[2].x + v[3].x);
        float s1x = (v[4].x + v[5].x) + (v[6].x + v[7].x);
        float s0y = (v[0].y + v[1].y) + (v[2].y + v[3].y);
        float s1y = (v[4].y + v[5].y) + (v[6].y + v[7].y);
        float s0z = (v[0].z + v[1].z) + (v[2].z + v[3].z);
        float s1z = (v[4].z + v[5].z) + (v[6].z + v[7].z);
        float s0w = (v[0].w + v[1].w) + (v[2].w + v[3].w);
        float s1w = (v[4].w + v[5].w) + (v[6].w + v[7].w);
        c0 += s0x + s1x;  c1 += s0y + s1y;
        c2 += s0z + s1z;  c3 += s0w + s1w;
        if (++grp == 4) {                 // flush every 32 rows
            a0 += c0; a1 += c1; a2 += c2; a3 += c3;
            c0 = c1 = c2 = c3 = 0.f; grp = 0;
        }
    }
    for (; row < r1; row++) {
        float4 v = __ldcs(&w4[(size_t)row * 1024]);
        c0 += v.x; c1 += v.y; c2 += v.z; c3 += v.w;
    }
    a0 += c0; a1 += c1; a2 += c2; a3 += c3;
    int s = 4 * t;
    atomicAdd(&g_sums[s + 0], a0);
    atomicAdd(&g_sums[s + 1], a1);
    atomicAdd(&g_sums[s + 2], a2);
    atomicAdd(&g_sums[s + 3], a3);
}

// ====== Kernel 2: rank -> KV L2-prefetch -> barrier -> build -> gather =====
__global__ void __launch_bounds__(NTHR, 1)
k_tail(const float4* __restrict__ keys,
       const float4* __restrict__ vals,
       float4* __restrict__ out) {
    __shared__ unsigned long long sj[NCAND];   // all candidate sums
    __shared__ int s_keep[NKEEP];              // full sorted keep list
    __shared__ int warpsum[32];

    const int t = threadIdx.x;
    const int b = blockIdx.x;
    const int lane = t & 31, w = t >> 5;

    // ---- Phase B: rank via pairwise count (no atomics) --------------------
    // Positive doubles -> u64 bit order isomorphic. Tie-break (equal value,
    // lower index wins) matches jax.lax.top_k. Block owns 25 candidates,
    // one warp per candidate; count loop unrolled x4.
    for (int k = t; k < NCAND; k += NTHR)
        sj[k] = __double_as_longlong(__ldcg(&g_sums[START + k]));
    __syncthreads();
    if (w < ICH) {
        int i = b * ICH + w;
        if (i < NCAND) {
            unsigned long long vi = sj[i];
            int cnt = 0;
            int j = lane;
            for (; j + 96 < NCAND; j += 128) {
                unsigned long long v0 = sj[j];
                unsigned long long v1 = sj[j + 32];
                unsigned long long v2 = sj[j + 64];
                unsigned long long v3 = sj[j + 96];
                cnt += (v0 > vi || (v0 == vi && j       < i));
                cnt += (v1 > vi || (v1 == vi && j + 32  < i));
                cnt += (v2 > vi || (v2 == vi && j + 64  < i));
                cnt += (v3 > vi || (v3 == vi && j + 96  < i));
            }
            for (; j < NCAND; j += 32) {
                unsigned long long vj = sj[j];
                cnt += (vj > vi || (vj == vi && j < i));
            }
            #pragma unroll
            for (int o = 16; o; o >>= 1)
                cnt += __shfl_down_sync(0xFFFFFFFFu, cnt, o);
            if (lane == 0) g_rank[i] = cnt;
        }
    }

    // ---- Phase P: stream KV through L2 (pure-read prefetch, 32 MB) --------
    // DRAM is idle during rank; after this the gather's scattered reads hit
    // L2 (~230cyc) instead of DRAM (~600cyc). Sink write defeats DCE.
    {
        const int f0 = (int)((long long)KVF4 * b / NBLK);
        const int f1 = (int)((long long)KVF4 * (b + 1) / NBLK);
        float acc = 0.f;
        int i = f0 + t;
        for (; i + 3 * NTHR < f1; i += 4 * NTHR) {
            float4 k0 = __ldcg(&keys[i]);
            float4 k1 = __ldcg(&keys[i + NTHR]);
            float4 k2 = __ldcg(&keys[i + 2 * NTHR]);
            float4 k3 = __ldcg(&keys[i + 3 * NTHR]);
            float4 u0 = __ldcg(&vals[i]);
            float4 u1 = __ldcg(&vals[i + NTHR]);
            float4 u2 = __ldcg(&vals[i + 2 * NTHR]);
            float4 u3 = __ldcg(&vals[i + 3 * NTHR]);
            acc += (k0.x + k1.x) + (k2.x + k3.x)
                 + (u0.x + u1.x) + (u2.x + u3.x);
        }
        for (; i < f1; i += NTHR)
            acc += __ldcg(&keys[i]).x + __ldcg(&vals[i]).x;
        if (t == 0) g_dummy[b] = acc;   // harmless sink (never read)
    }

    // ---- grid barrier (all 148 blocks co-resident) ------------------------
    __syncthreads();
    if (t == 0) {
        __threadfence();
        atomicAdd(&g_cnt, 1);
        while (*(volatile int*)&g_cnt < NBLK) { }
        __threadfence();
    }
    __syncthreads();

    // ---- Phase C: build full sorted keep list (redundant per block) -------
    // keep = [0..3] ++ heavy(sorted asc, in (4,3687)) ++ [3687..4095]
    {
        int base = 4 * t;
        int rk[4];
        #pragma unroll
        for (int k = 0; k < 4; k++) {
            int c = base + k;
            rk[k] = (c < NCAND) ? __ldcg(&g_rank[c]) : HEAVY;
        }
        int f[4], loc = 0;
        #pragma unroll
        for (int k = 0; k < 4; k++) {
            f[k] = (rk[k] < HEAVY) ? 1 : 0;
            loc += f[k];
        }
        int v = loc;
        #pragma unroll
        for (int o = 1; o < 32; o <<= 1) {
            int n = __shfl_up_sync(0xFFFFFFFFu, v, o);
            if (lane >= o) v += n;
        }
        if (lane == 31) warpsum[w] = v;
        __syncthreads();
        if (w == 0) {
            int s = warpsum[lane];
            #pragma unroll
            for (int o = 1; o < 32; o <<= 1) {
                int n = __shfl_up_sync(0xFFFFFFFFu, s, o);
                if (lane >= o) s += n;
            }
            warpsum[lane] = s;
        }
        __syncthreads();
        int pos = START + v - loc + (w > 0 ? warpsum[w - 1] : 0);
        #pragma unroll
        for (int k = 0; k < 4; k++) {
            if (f[k]) { s_keep[pos] = START + base + k; pos++; }
        }
        if (t < START) s_keep[t] = t;
        if (t < SEQ - RSTART) s_keep[START + HEAVY + t] = RSTART + t;
    }
    __syncthreads();

    // ---- Phase D: full gather (54 MB), reads now L2-resident --------------
    {
        const int stride = NBLK * NTHR;         // 151552
        int v = b * NTHR + t;
        for (; v + 3 * stride < TOTAL_G; v += 4 * stride) {
            float4 d[4];
            #pragma unroll
            for (int k = 0; k < 4; k++) {
                int vv  = v + k * stride;
                int d4  = vv & 31;
                int row = vv >> 5;
                int tensor = row / (HEADS * NKEEP);
                int rem = row - tensor * (HEADS * NKEEP);
                int h   = rem / NKEEP;
                int r   = rem - h * NKEEP;
                int s   = s_keep[r];
                const float4* __restrict__ src = tensor ? vals : keys;
                d[k] = __ldg(&src[(((size_t)h * SEQ + s) << 5) + d4]);
            }
            #pragma unroll
            for (int k = 0; k < 4; k++) out[v + k * stride] = d[k];
        }
        for (; v < TOTAL_G; v += stride) {
            int d4  = v & 31;
            int row = v >> 5;
            int tensor = row / (HEADS * NKEEP);
            int rem = row - tensor * (HEADS * NKEEP);
            int h   = rem / NKEEP;
            int r   = rem - h * NKEEP;
            int s   = s_keep[r];
            const float4* __restrict__ src = tensor ? vals : keys;
            out[v] = __ldg(&src[(((size_t)h * SEQ + s) << 5) + d4]);
        }
    }

    // ---- epilogue: last block resets scratch for the next call ------------
    __syncthreads();
    __shared__ int s_last;
    if (t == 0) {
        __threadfence();
        s_last = (atomicAdd(&g_done, 1) == NBLK - 1) ? 1 : 0;
    }
    __syncthreads();
    if (s_last) {
        for (int i = t; i < SEQ; i += NTHR) g_sums[i] = 0.0;
        if (t == 0) { g_cnt = 0; g_done = 0; }
    }
}

extern "C" void kernel_launch(void* const* d_in, const int* in_sizes, int n_in,
                              void* d_out, int out_size) {
    const float* keys = (const float*)d_in[0];   // (1,32,4096,128)
    const float* vals = (const float*)d_in[1];   // (1,32,4096,128)
    const float* attn = (const float*)d_in[2];   // (1,32,1024,4096)
    float* out = (float*)d_out;                  // 2*32*822*128 f32

    k_colsum<<<NBLK, NTHR>>>(attn);
    k_tail<<<NBLK, NTHR>>>((const float4*)keys, (const float4*)vals,
                           (float4*)out);
}

// round 12
// speedup vs baseline: 1.2000x; 1.2000x over previous
#include <cuda_runtime.h>

// Problem constants (B=1, H=32, Q=1024, S=4096, D=128)
#define SEQ      4096
#define ROWS     32768      // B*H*Q rows of attn_weights
#define START    4
#define HEAVY    409        // int(4096*0.1)
#define RSTART   3687       // 4096 - min(409,512)
#define NCAND    3683       // RSTART - START
#define NKEEP    822        // 4 + 409 + 409
#define HEADS    32
#define NBLK     148        // one exact wave
#define NTHR     1024
#define TOTAL_G  (2*HEADS*NKEEP*32)   // full gather float4 count = 1,683,456
#define SETCAP   256        // max prefix-tie set (expected ~1-5)

// Scratch. g_sums is atomically accumulated so it MUST be zero at entry:
// in k_tail, the last block to FINISH LOADING g_sums re-zeroes it (arrive
// counter, no waiting). g_done reset by that same block.
__device__ double g_sums[SEQ];
__device__ int    g_done;

// ================= Kernel 1: column sums (512 MB PURE READ stream) =========
// 148 blocks, contiguous row range each (measured ~82us @ ~83% DRAM).
// Thread t owns columns [4t,4t+4) via float4; 8 front-batched LDG.128
// (MLP=8); __ldcs (no reuse). fp32 over 32 rows flushed into fp64 keeps the
// mean accurate to ~1e-8 rel (top-k boundary gap ~1e-5); fp64 atomicAdd
// ordering noise ~1e-13 — selection identical to reference (rel_err 0.0).
__global__ void __launch_bounds__(NTHR, 1) k_colsum(const float* __restrict__ w) {
    const int t = threadIdx.x;
    const int b = blockIdx.x;
    const int r0 = (int)((long long)ROWS * b / NBLK);
    const int r1 = (int)((long long)ROWS * (b + 1) / NBLK);
    const float4* __restrict__ w4 = (const float4*)w + t;
    double a0 = 0, a1 = 0, a2 = 0, a3 = 0;
    float  c0 = 0, c1 = 0, c2 = 0, c3 = 0;
    int row = r0, grp = 0;
    for (; row + 8 <= r1; row += 8) {
        float4 v[8];
        #pragma unroll
        for (int k = 0; k < 8; k++)
            v[k] = __ldcs(&w4[(size_t)(row + k) * 1024]);
        float s0x = (v[0].x + v[1].x) + (v[2].x + v[3].x);
        float s1x = (v[4].x + v[5].x) + (v[6].x + v[7].x);
        float s0y = (v[0].y + v[1].y) + (v[2].y + v[3].y);
        float s1y = (v[4].y + v[5].y) + (v[6].y + v[7].y);
        float s0z = (v[0].z + v[1].z) + (v[2].z + v[3].z);
        float s1z = (v[4].z + v[5].z) + (v[6].z + v[7].z);
        float s0w = (v[0].w + v[1].w) + (v[2].w + v[3].w);
        float s1w = (v[4].w + v[5].w) + (v[6].w + v[7].w);
        c0 += s0x + s1x;  c1 += s0y + s1y;
        c2 += s0z + s1z;  c3 += s0w + s1w;
        if (++grp == 4) {                 // flush every 32 rows
            a0 += c0; a1 += c1; a2 += c2; a3 += c3;
            c0 = c1 = c2 = c3 = 0.f; grp = 0;
        }
    }
    for (; row < r1; row++) {
        float4 v = __ldcs(&w4[(size_t)row * 1024]);
        c0 += v.x; c1 += v.y; c2 += v.z; c3 += v.w;
    }
    a0 += c0; a1 += c1; a2 += c2; a3 += c3;
    int s = 4 * t;
    atomicAdd(&g_sums[s + 0], a0);
    atomicAdd(&g_sums[s + 1], a1);
    atomicAdd(&g_sums[s + 2], a2);
    atomicAdd(&g_sums[s + 3], a3);
}

// ==== Kernel 2: per-block independent select -> build -> gather ============
// No grid barrier, no cross-block exchange. Every block computes the SAME
// selection from g_sums via 3-level radix-select (11 bits/level, u64 keys,
// bit-order isomorphic for positive doubles) + exact tie subset using the
// reference comparator (value desc, index asc) == jax.lax.top_k.
__global__ void __launch_bounds__(NTHR, 1)
k_tail(const float4* __restrict__ keys,
       const float4* __restrict__ vals,
       float4* __restrict__ out) {
    __shared__ unsigned long long sj[NCAND];   // all candidate sums
    __shared__ int  hist[2048];
    __shared__ int  s_keep[NKEEP];             // full sorted keep list
    __shared__ int  warpsum[32];
    __shared__ int  s_bin, s_R, s_setcnt, s_zero;
    __shared__ int  s_setidx[SETCAP];
    __shared__ unsigned char s_take[SETCAP];

    const int t = threadIdx.x;
    const int b = blockIdx.x;
    const int lane = t & 31, w = t >> 5;

    for (int k = t; k < NCAND; k += NTHR)
        sj[k] = __double_as_longlong(__ldcg(&g_sums[START + k]));
    if (t == 0) s_setcnt = 0;
    __syncthreads();
    // Arrive counter: last block whose load completed will zero g_sums at
    // the end (all other blocks have finished reading by then).
    if (t == 0) {
        __threadfence();
        s_zero = (atomicAdd(&g_done, 1) == NBLK - 1) ? 1 : 0;
    }

    // ---- Phase S: radix-select the HEAVY-th largest threshold prefix ------
    unsigned long long pfx = 0;
    int R = HEAVY;
    #pragma unroll
    for (int lvl = 0; lvl < 3; lvl++) {
        const int shift = 53 - 11 * lvl;       // 53, 42, 31
        for (int i = t; i < 2048; i += NTHR) hist[i] = 0;
        __syncthreads();
        for (int k = t; k < NCAND; k += NTHR) {
            unsigned long long key = sj[k];
            if (lvl == 0 || (key >> (shift + 11)) == pfx)
                atomicAdd(&hist[(int)((key >> shift) & 0x7FF)], 1);
        }
        __syncthreads();
        // Suffix sums T(bin) = #keys(in prefix) with bin-bits >= bin.
        const int r0 = 2 * t, r1 = 2 * t + 1;  // reversed order index
        const int v0 = hist[2047 - r0];
        const int v1 = hist[2047 - r1];
        const int pair = v0 + v1;
        int v = pair;
        #pragma unroll
        for (int o = 1; o < 32; o <<= 1) {
            int n = __shfl_up_sync(0xFFFFFFFFu, v, o);
            if (lane >= o) v += n;
        }
        if (lane == 31) warpsum[w] = v;
        __syncthreads();
        if (w == 0) {
            int s = warpsum[lane];
            #pragma unroll
            for (int o = 1; o < 32; o <<= 1) {
                int n = __shfl_up_sync(0xFFFFFFFFu, s, o);
                if (lane >= o) s += n;
            }
            warpsum[lane] = s;
        }
        __syncthreads();
        const int excl = v - pair + (w > 0 ? warpsum[w - 1] : 0);
        const int T0 = excl + v0;              // T at bin 2047-r0
        const int T1 = excl + pair;            // T at bin 2047-r1
        if (T0 - v0 < R && R <= T0) { s_bin = 2047 - r0; s_R = R - (T0 - v0); }
        if (T1 - v1 < R && R <= T1) { s_bin = 2047 - r1; s_R = R - (T1 - v1); }
        __syncthreads();
        pfx = (pfx << 11) | (unsigned long long)s_bin;
        R = s_R;
        __syncthreads();
    }
    // pfx = top-33-bit threshold prefix; need R more from exact tie subset.
    for (int k = t; k < NCAND; k += NTHR) {
        if ((sj[k] >> 31) == pfx) {
            int p = atomicAdd(&s_setcnt, 1);
            if (p < SETCAP) s_setidx[p] = k;
        }
    }
    __syncthreads();
    const int setcnt = min(s_setcnt, SETCAP);
    if (w == 0) {
        for (int m = lane; m < setcnt; m += 32) {
            int im = s_setidx[m];
            unsigned long long km = sj[im];
            int rk = 0;
            for (int j = 0; j < setcnt; j++) {
                int ij = s_setidx[j];
                unsigned long long kj = sj[ij];
                rk += (kj > km || (kj == km && ij < im)) ? 1 : 0;
            }
            s_take[m] = (rk < R) ? 1 : 0;
        }
    }
    __syncthreads();

    // ---- Phase C: build full sorted keep list --------------------------
    // keep = [0..3] ++ heavy(sorted asc) ++ [3687..4095] (globally sorted)
    {
        int base = 4 * t;
        int f[4], loc = 0;
        #pragma unroll
        for (int k = 0; k < 4; k++) {
            int c = base + k;
            int fl = 0;
            if (c < NCAND) {
                unsigned long long hk = sj[c] >> 31;
                if (hk > pfx) fl = 1;
                else if (hk == pfx) {
                    for (int m = 0; m < setcnt; m++)
                        if (s_setidx[m] == c) { fl = s_take[m]; break; }
                }
            }
            f[k] = fl; loc += fl;
        }
        int v = loc;
        #pragma unroll
        for (int o = 1; o < 32; o <<= 1) {
            int n = __shfl_up_sync(0xFFFFFFFFu, v, o);
            if (lane >= o) v += n;
        }
        if (lane == 31) warpsum[w] = v;
        __syncthreads();
        if (w == 0) {
            int s = warpsum[lane];
            #pragma unroll
            for (int o = 1; o < 32; o <<= 1) {
                int n = __shfl_up_sync(0xFFFFFFFFu, s, o);
                if (lane >= o) s += n;
            }
            warpsum[lane] = s;
        }
        __syncthreads();
        int pos = START + v - loc + (w > 0 ? warpsum[w - 1] : 0);
        #pragma unroll
        for (int k = 0; k < 4; k++) {
            if (f[k]) { s_keep[pos] = START + base + k; pos++; }
        }
        if (t < START) s_keep[t] = t;
        if (t < SEQ - RSTART) s_keep[START + HEAVY + t] = RSTART + t;
    }
    __syncthreads();

    // ---- Phase D: full gather (54 MB), unroll-4 (proven R6 form) ----------
    {
        const int stride = NBLK * NTHR;         // 151552
        int v = b * NTHR + t;
        for (; v + 3 * stride < TOTAL_G; v += 4 * stride) {
            float4 d[4];
            #pragma unroll
            for (int k = 0; k < 4; k++) {
                int vv  = v + k * stride;
                int d4  = vv & 31;
                int row = vv >> 5;
                int tensor = row / (HEADS * NKEEP);
                int rem = row - tensor * (HEADS * NKEEP);
                int h   = rem / NKEEP;
                int r   = rem - h * NKEEP;
                int s   = s_keep[r];
                const float4* __restrict__ src = tensor ? vals : keys;
                d[k] = __ldcs(&src[(((size_t)h * SEQ + s) << 5) + d4]);
            }
            #pragma unroll
            for (int k = 0; k < 4; k++) out[v + k * stride] = d[k];
        }
        for (; v < TOTAL_G; v += stride) {
            int d4  = v & 31;
            int row = v >> 5;
            int tensor = row / (HEADS * NKEEP);
            int rem = row - tensor * (HEADS * NKEEP);
            int h   = rem / NKEEP;
            int r   = rem - h * NKEEP;
            int s   = s_keep[r];
            const float4* __restrict__ src = tensor ? vals : keys;
            out[v] = __ldcs(&src[(((size_t)h * SEQ + s) << 5) + d4]);
        }
    }

    // ---- epilogue: designated block re-zeroes g_sums for next call --------
    __syncthreads();
    if (s_zero) {
        for (int i = t; i < SEQ; i += NTHR) g_sums[i] = 0.0;
        if (t == 0) g_done = 0;
    }
}

extern "C" void kernel_launch(void* const* d_in, const int* in_sizes, int n_in,
                              void* d_out, int out_size) {
    const float* keys = (const float*)d_in[0];   // (1,32,4096,128)
    const float* vals = (const float*)d_in[1];   // (1,32,4096,128)
    const float* attn = (const float*)d_in[2];   // (1,32,1024,4096)
    float* out = (float*)d_out;                  // 2*32*822*128 f32

    k_colsum<<<NBLK, NTHR>>>(attn);
    k_tail<<<NBLK, NTHR>>>((const float4*)keys, (const float4*)vals,
                           (float4*)out);
}